// round 3
// baseline (speedup 1.0000x reference)
#include <cuda_runtime.h>
#include <cstdint>

#define FULLMASK 0xffffffffu

// Scratch (device globals — no allocation allowed)
__device__ float g_feat[32 * 2048];        // [b][2048]  (pos | neg features)
__device__ float g_part[32 * 32 * 1024];   // [kg][b][c] split-K partials

// Monotone float -> uint key (ascending). key(-f) == ~key(f).
__device__ __forceinline__ unsigned key_encode(float f) {
    unsigned u = __float_as_uint(f);
    return (u & 0x80000000u) ? ~u : (u | 0x80000000u);
}
__device__ __forceinline__ float key_decode(unsigned k) {
    unsigned u = (k & 0x80000000u) ? (k & 0x7fffffffu) : ~k;
    return __uint_as_float(u);
}

// ---------------------------------------------------------------------------
// Dual suffix-scan + threshold locate over two histograms of 256*BP bins.
// Thread tid owns bins [tid*BP, tid*BP+BP). Unique crossing thread updates
// s_thr (OR in bin index << shift) and s_rem. Contains one __syncthreads.
// ---------------------------------------------------------------------------
template <int BP>
__device__ __forceinline__ void scan_pair(const unsigned* __restrict__ h0,
                                          const unsigned* __restrict__ h1,
                                          unsigned rem0, unsigned rem1, int shift,
                                          unsigned* s_thr, unsigned* s_rem,
                                          unsigned (*s_wtot)[8]) {
    const int tid = threadIdx.x, lane = tid & 31, wid = tid >> 5;
    unsigned c0[BP], c1[BP], S0 = 0u, S1 = 0u;
    #pragma unroll
    for (int j = 0; j < BP; ++j) {
        c0[j] = h0[tid * BP + j]; S0 += c0[j];
        c1[j] = h1[tid * BP + j]; S1 += c1[j];
    }
    unsigned i0 = S0, i1 = S1;
    #pragma unroll
    for (int o = 1; o < 32; o <<= 1) {
        unsigned v0 = __shfl_down_sync(FULLMASK, i0, o);
        unsigned v1 = __shfl_down_sync(FULLMASK, i1, o);
        if (lane + o < 32) { i0 += v0; i1 += v1; }
    }
    if (lane == 0) { s_wtot[0][wid] = i0; s_wtot[1][wid] = i1; }
    __syncthreads();
    unsigned hi0 = 0u, hi1 = 0u;
    #pragma unroll
    for (int w = 0; w < 8; ++w)
        if (w > wid) { hi0 += s_wtot[0][w]; hi1 += s_wtot[1][w]; }
    unsigned cum0 = (i0 - S0) + hi0;   // count in bins strictly above mine
    unsigned cum1 = (i1 - S1) + hi1;
    #pragma unroll
    for (int j = BP - 1; j >= 0; --j) {
        if (cum0 < rem0 && cum0 + c0[j] >= rem0) {
            s_thr[0] |= (unsigned)(tid * BP + j) << shift;
            s_rem[0]  = rem0 - cum0;
        }
        cum0 += c0[j];
        if (cum1 < rem1 && cum1 + c1[j] >= rem1) {
            s_thr[1] |= (unsigned)(tid * BP + j) << shift;
            s_rem[1]  = rem1 - cum1;
        }
        cum1 += c1[j];
    }
}

// ---------------------------------------------------------------------------
// Kernel 1: per batch row b — row norms + exact top16/bottom16 sums of the
// histo row via 3-pass 11/11/10-bit radix select (both selections concurrent),
// then emit feat[b] = [pos(1024) | neg(1024)].  grid 32, block 256.
// ---------------------------------------------------------------------------
__global__ void __launch_bounds__(256) k1_stats_feat(
        const float* __restrict__ f_rad, const float* __restrict__ f_histo) {
    const int b    = blockIdx.x;
    const int tid  = threadIdx.x;
    const int lane = tid & 31;
    const int wid  = tid >> 5;
    const float* __restrict__ hrow = f_histo + b * 2048;
    const float* __restrict__ rrow = f_rad   + b * 1024;

    __shared__ unsigned hist[2][2048];
    __shared__ unsigned s_thr[2], s_rem[2];
    __shared__ unsigned s_wtot[2][8];
    __shared__ float    s_red[4][8];
    __shared__ float    s_bcast[3];

    // Load histo row (8/thread) + rad row (4/thread), sums of squares.
    float hv[8];
    float ssh = 0.f, ssr = 0.f;
    #pragma unroll
    for (int u = 0; u < 8; ++u) {
        float v = hrow[u * 256 + tid];
        hv[u] = v;
        ssh += v * v;
    }
    #pragma unroll
    for (int u = 0; u < 4; ++u) {
        float v = rrow[u * 256 + tid];
        ssr += v * v;
    }
    unsigned keys[8];
    #pragma unroll
    for (int u = 0; u < 8; ++u) keys[u] = key_encode(hv[u]);

    unsigned* H0 = hist[0];
    unsigned* H1 = hist[1];
    unsigned* Hf = &hist[0][0];

    // ================= PASS 1: bits [21..31], 2048 bins =================
    #pragma unroll
    for (int u = 0; u < 16; ++u) Hf[tid + 256 * u] = 0u;
    if (tid < 2) { s_thr[tid] = 0u; s_rem[tid] = 16u; }
    __syncthreads();
    #pragma unroll
    for (int u = 0; u < 8; ++u) {
        atomicAdd(&H0[keys[u] >> 21], 1u);
        atomicAdd(&H1[(~keys[u]) >> 21], 1u);
    }
    __syncthreads();
    scan_pair<8>(H0, H1, 16u, 16u, 21, s_thr, s_rem, s_wtot);
    __syncthreads();

    // ================= PASS 2: bits [10..20], 2048 bins =================
    unsigned p0 = s_thr[0], p1 = s_thr[1];
    unsigned r0 = s_rem[0], r1 = s_rem[1];
    #pragma unroll
    for (int u = 0; u < 16; ++u) Hf[tid + 256 * u] = 0u;
    __syncthreads();
    #pragma unroll
    for (int u = 0; u < 8; ++u) {
        unsigned k = keys[u], kn = ~k;
        if ((k  & 0xFFE00000u) == p0) atomicAdd(&H0[(k  >> 10) & 0x7FFu], 1u);
        if ((kn & 0xFFE00000u) == p1) atomicAdd(&H1[(kn >> 10) & 0x7FFu], 1u);
    }
    __syncthreads();
    scan_pair<8>(H0, H1, r0, r1, 10, s_thr, s_rem, s_wtot);
    __syncthreads();

    // ================= PASS 3: bits [0..9], 1024 bins ====================
    p0 = s_thr[0]; p1 = s_thr[1];
    r0 = s_rem[0]; r1 = s_rem[1];
    #pragma unroll
    for (int u = 0; u < 8; ++u) Hf[tid + 256 * u] = 0u;
    __syncthreads();
    #pragma unroll
    for (int u = 0; u < 8; ++u) {
        unsigned k = keys[u], kn = ~k;
        if ((k  & 0xFFFFFC00u) == p0) atomicAdd(&H0[k  & 0x3FFu], 1u);
        if ((kn & 0xFFFFFC00u) == p1) atomicAdd(&H1[kn & 0x3FFu], 1u);
    }
    __syncthreads();
    scan_pair<4>(H0, H1, r0, r1, 0, s_thr, s_rem, s_wtot);
    __syncthreads();

    const unsigned T0 = s_thr[0], rem0 = s_rem[0];
    const unsigned T1 = s_thr[1], rem1 = s_rem[1];

    // Sums of strictly-greater elements for each selection.
    float sum0 = 0.f, sum1 = 0.f;
    #pragma unroll
    for (int u = 0; u < 8; ++u) {
        if (keys[u] > T0)    sum0 += hv[u];
        if ((~keys[u]) > T1) sum1 += (-hv[u]);
    }

    // Block-reduce {ssh, ssr, sum0, sum1}
    #pragma unroll
    for (int o = 16; o; o >>= 1) {
        ssh  += __shfl_xor_sync(FULLMASK, ssh,  o);
        ssr  += __shfl_xor_sync(FULLMASK, ssr,  o);
        sum0 += __shfl_xor_sync(FULLMASK, sum0, o);
        sum1 += __shfl_xor_sync(FULLMASK, sum1, o);
    }
    if (lane == 0) {
        s_red[0][wid] = ssh;  s_red[1][wid] = ssr;
        s_red[2][wid] = sum0; s_red[3][wid] = sum1;
    }
    __syncthreads();
    if (tid == 0) {
        float a0 = 0.f, a1 = 0.f, a2 = 0.f, a3 = 0.f;
        #pragma unroll
        for (int w = 0; w < 8; ++w) {
            a0 += s_red[0][w]; a1 += s_red[1][w];
            a2 += s_red[2][w]; a3 += s_red[3][w];
        }
        float nh  = fmaxf(sqrtf(a0), 1e-12f);
        float nr  = fmaxf(sqrtf(a1), 1e-12f);
        float top = a2 + (float)rem0 * key_decode(T0);   // sum of top16(h)
        float bng = a3 + (float)rem1 * key_decode(T1);   // sum of top16(-h)
        s_bcast[0] = 1.f / nr;
        s_bcast[1] = top  / (16.f * nh);    // T  = mean(top16(h_norm))
        s_bcast[2] = -bng / (16.f * nh);    // Bt = mean(bottom16(h_norm))
    }
    __syncthreads();

    const float inv_nr = s_bcast[0];
    const float T      = s_bcast[1];
    const float Bt     = s_bcast[2];
    float* __restrict__ fout = g_feat + b * 2048;
    #pragma unroll
    for (int u = 0; u < 4; ++u) {
        int   i  = u * 256 + tid;
        float rv = rrow[i] * inv_nr;
        float pm, nm;
        if (rv >= 0.f) { pm = rv * T;  nm = -rv * Bt; }
        else           { pm = rv * Bt; nm = -rv * T;  }
        fout[i]        = pm;
        fout[1024 + i] = nm;
    }
}

// ---------------------------------------------------------------------------
// Kernel 2: split-K fp32 GEMM partials. Block tile 32b x 64c x 64k, 32 threads,
// thread tile 8b x 8c interleaved (b = bl+4i, c = cl+8j). Smem rows padded to
// 68 floats -> float4 bank-group = (row+q) mod 8: conflict-free vector loads.
// grid (16 cblk, 32 kg).
// ---------------------------------------------------------------------------
__global__ void __launch_bounds__(32) k2_gemm(const float* __restrict__ W) {
    __shared__ float Ws[64 * 68];
    __shared__ float Fs[32 * 68];
    const int tid = threadIdx.x;
    const int c0  = blockIdx.x * 64;
    const int kg  = blockIdx.y;
    const int k0  = kg * 64;

    // Load W tile 64c x 64k (1024 float4) and feat tile 32b x 64k (512 float4).
    #pragma unroll
    for (int it = 0; it < 32; ++it) {
        int idx = it * 32 + tid;          // float4 id
        int r   = idx >> 4;               // 0..63
        int q   = idx & 15;               // 0..15
        float4 v = *(const float4*)&W[(c0 + r) * 2048 + k0 + q * 4];
        *(float4*)&Ws[r * 68 + q * 4] = v;
    }
    #pragma unroll
    for (int it = 0; it < 16; ++it) {
        int idx = it * 32 + tid;
        int r   = idx >> 4;               // 0..31
        int q   = idx & 15;
        float4 v = *(const float4*)&g_feat[r * 2048 + k0 + q * 4];
        *(float4*)&Fs[r * 68 + q * 4] = v;
    }
    __syncthreads();

    const int bl = tid >> 3;   // 0..3 : b rows  bl, bl+4, ..., bl+28
    const int cl = tid & 7;    // 0..7 : c cols  cl, cl+8, ..., cl+56

    float acc[8][8];
    #pragma unroll
    for (int i = 0; i < 8; ++i)
        #pragma unroll
        for (int j = 0; j < 8; ++j) acc[i][j] = 0.f;

    #pragma unroll
    for (int kq = 0; kq < 16; ++kq) {
        float4 f[8], w[8];
        #pragma unroll
        for (int i = 0; i < 8; ++i) f[i] = *(const float4*)&Fs[(bl + 4 * i) * 68 + kq * 4];
        #pragma unroll
        for (int j = 0; j < 8; ++j) w[j] = *(const float4*)&Ws[(cl + 8 * j) * 68 + kq * 4];
        #pragma unroll
        for (int i = 0; i < 8; ++i)
            #pragma unroll
            for (int j = 0; j < 8; ++j) {
                acc[i][j] = fmaf(f[i].x, w[j].x, acc[i][j]);
                acc[i][j] = fmaf(f[i].y, w[j].y, acc[i][j]);
                acc[i][j] = fmaf(f[i].z, w[j].z, acc[i][j]);
                acc[i][j] = fmaf(f[i].w, w[j].w, acc[i][j]);
            }
    }

    float* __restrict__ outp = g_part + kg * (32 * 1024) + c0;
    #pragma unroll
    for (int i = 0; i < 8; ++i) {
        #pragma unroll
        for (int j = 0; j < 8; ++j)
            outp[(bl + 4 * i) * 1024 + cl + 8 * j] = acc[i][j];
    }
}

// ---------------------------------------------------------------------------
// Kernel 3: reduce 32 split-K partials + bias + token * flag. grid 64, blk 128.
// ---------------------------------------------------------------------------
__global__ void __launch_bounds__(128) k3_reduce(
        const float* __restrict__ bias, const float* __restrict__ token,
        const unsigned char* __restrict__ rad_mask,
        const unsigned char* __restrict__ histo_mask,
        float* __restrict__ out) {
    int gid = blockIdx.x * 128 + threadIdx.x;   // float4 id 0..8191
    int b   = gid >> 8;
    int c4  = gid & 255;

    float4 acc = *(const float4*)&bias[c4 * 4];
    #pragma unroll
    for (int g = 0; g < 32; ++g) {
        float4 p = *(const float4*)&g_part[g * 32768 + b * 1024 + c4 * 4];
        acc.x += p.x; acc.y += p.y; acc.z += p.z; acc.w += p.w;
    }
    float flag = (rad_mask[b] != 0 && histo_mask[b] != 0) ? 0.f : 1.f;
    float4 tk  = *(const float4*)&token[c4 * 4];
    acc.x += tk.x * flag; acc.y += tk.y * flag;
    acc.z += tk.z * flag; acc.w += tk.w * flag;
    *(float4*)&out[b * 1024 + c4 * 4] = acc;
}

// ---------------------------------------------------------------------------
extern "C" void kernel_launch(void* const* d_in, const int* in_sizes, int n_in,
                              void* d_out, int out_size) {
    const float*         f_rad      = (const float*)d_in[0];
    const float*         f_histo    = (const float*)d_in[1];
    const unsigned char* rad_mask   = (const unsigned char*)d_in[2];
    const unsigned char* histo_mask = (const unsigned char*)d_in[3];
    const float*         W          = (const float*)d_in[4];
    const float*         bias       = (const float*)d_in[5];
    const float*         token      = (const float*)d_in[6];
    float*               out        = (float*)d_out;

    k1_stats_feat<<<32, 256>>>(f_rad, f_histo);
    k2_gemm<<<dim3(16, 32), 32>>>(W);
    k3_reduce<<<64, 128>>>(bias, token, rad_mask, histo_mask, out);
}